// round 11
// baseline (speedup 1.0000x reference)
#include <cuda_runtime.h>
#include <cuda_fp16.h>
#include <mma.h>
#include <math.h>
#include <stdint.h>

using namespace nvcuda;

#define NCAM 6
#define NH   8
#define NP   4
#define DD   256
#define HH   20
#define WW   40
#define HWW  800
#define LQ   4800
#define HDIM 32
#define NOFF 384
#define NKV  512
#define TWO_PI 6.283185307179586f

// ------------------------- scratch (static device arrays) -------------------
__device__ float  g_res  [LQ*DD];
__device__ float  g_srcb [LQ*DD];
__device__ float  g_qry  [LQ*DD];
__device__ __half g_kvh  [(size_t)LQ*NKV];
__device__ float  g_offb [LQ*NOFF];
__device__ float  g_posb [HWW*DD];
__device__ float  g_part [NCAM*16*DD];
__device__ float  g_meanb[NCAM*DD];
__device__ float  g_gtokb[NCAM*DD];
__device__ float  g_attb [LQ*DD];
__device__ float  g_t1b  [LQ*DD];
__device__ float  g_t2b  [LQ*DD];
__device__ float  g_lnb  [LQ*DD];
__device__ float  g_wc   [DD*DD];
__device__ float  g_bc   [DD];
__device__ float  g_wkv  [NKV*DD];
__device__ float  g_bkv  [NKV];

// ------------------------- cp.async helpers ---------------------------------
__device__ __forceinline__ void cp_async16(uint32_t saddr, const void* gptr) {
    asm volatile("cp.async.cg.shared.global [%0], [%1], 16;" :: "r"(saddr), "l"(gptr));
}
__device__ __forceinline__ void cp_commit() {
    asm volatile("cp.async.commit_group;");
}
template<int N>
__device__ __forceinline__ void cp_wait() {
    asm volatile("cp.async.wait_group %0;" :: "n"(N));
}

// ------------------------- small prep kernels -------------------------------

__global__ void pack_kvw_kernel(const float* __restrict__ key_w, const float* __restrict__ val_w,
                                const float* __restrict__ key_b, const float* __restrict__ val_b,
                                float* __restrict__ wkv, float* __restrict__ bkv)
{
    int n = blockIdx.x;
    int c = threadIdx.x;
    int head = n >> 6, ch = n & 63;
    const float* src = (ch < 32) ? (key_w + (size_t)(head*32 + ch)*DD)
                                 : (val_w + (size_t)(head*32 + ch - 32)*DD);
    wkv[(size_t)n*DD + c] = src[c];
    if (c == 0)
        bkv[n] = (ch < 32) ? key_b[head*32 + ch] : val_b[head*32 + ch - 32];
}

__global__ void transpose_in_kernel(const float* __restrict__ x, float* __restrict__ res)
{
    __shared__ float tile[32][33];
    int cam = blockIdx.z;
    int c0  = blockIdx.y * 32;
    int p0  = blockIdx.x * 32;
    int tx = threadIdx.x, ty = threadIdx.y;
    #pragma unroll
    for (int i = ty; i < 32; i += 8)
        tile[i][tx] = x[(size_t)(cam*DD + c0 + i)*HWW + p0 + tx];
    __syncthreads();
    #pragma unroll
    for (int i = ty; i < 32; i += 8)
        res[(size_t)(cam*HWW + p0 + i)*DD + c0 + tx] = tile[tx][i];
}

__global__ void pos_kernel(float* __restrict__ pos)
{
    int pix = blockIdx.x;
    int c   = threadIdx.x;
    int i = pix / WW, j = pix % WW;
    float v; int cc;
    if (c < 128) { v = (float)(i + 1) / (20.0f + 1e-6f) * TWO_PI; cc = c; }
    else         { v = (float)(j + 1) / (40.0f + 1e-6f) * TWO_PI; cc = c - 128; }
    float expo = (2.0f * (float)(cc / 2)) / 128.0f;
    float dt = powf(10000.0f, expo);
    float ph = v / dt;
    pos[(size_t)pix*DD + c] = (cc & 1) ? cosf(ph) : sinf(ph);
}

// Wc = conv1_w @ out_w  (NN gemm, 256x256x256)
__global__ __launch_bounds__(256)
void fold_w_kernel(const float* __restrict__ A, const float* __restrict__ B,
                   float* __restrict__ C)
{
    __shared__ float As[16][68];
    __shared__ float Bs[16][68];
    int tid = threadIdx.x;
    int bm = blockIdx.y * 64, bn = blockIdx.x * 64;
    int ra = tid >> 2;
    int ca = (tid & 3) << 2;
    int br = tid >> 4;
    int bcol = (tid & 15) << 2;
    int tr = (tid >> 4) << 2;
    int tc = (tid & 15) << 2;

    float acc[4][4];
    #pragma unroll
    for (int i = 0; i < 4; ++i)
        #pragma unroll
        for (int j = 0; j < 4; ++j) acc[i][j] = 0.f;

    for (int k0 = 0; k0 < DD; k0 += 16) {
        float4 a = *(const float4*)(A + (size_t)(bm + ra)*DD + k0 + ca);
        As[ca+0][ra] = a.x; As[ca+1][ra] = a.y; As[ca+2][ra] = a.z; As[ca+3][ra] = a.w;
        float4 b = *(const float4*)(B + (size_t)(k0 + br)*DD + bn + bcol);
        *(float4*)&Bs[br][bcol] = b;
        __syncthreads();
        #pragma unroll
        for (int kk = 0; kk < 16; ++kk) {
            float4 av = *(const float4*)&As[kk][tr];
            float4 bv = *(const float4*)&Bs[kk][tc];
            float ar[4] = {av.x, av.y, av.z, av.w};
            float br2[4] = {bv.x, bv.y, bv.z, bv.w};
            #pragma unroll
            for (int i = 0; i < 4; ++i)
                #pragma unroll
                for (int j = 0; j < 4; ++j) acc[i][j] = fmaf(ar[i], br2[j], acc[i][j]);
        }
        __syncthreads();
    }
    #pragma unroll
    for (int i = 0; i < 4; ++i)
        *(float4*)(C + (size_t)(bm + tr + i)*DD + bn + tc) = *(float4*)acc[i];
}

__global__ void fold_b_kernel(const float* __restrict__ conv1_w, const float* __restrict__ out_b,
                              const float* __restrict__ conv1_b, float* __restrict__ bc)
{
    int w = threadIdx.x >> 5, lane = threadIdx.x & 31;
    int o = blockIdx.x * 8 + w;
    const float* cw = conv1_w + (size_t)o*DD;
    float s = 0.f;
    #pragma unroll
    for (int j = 0; j < 8; ++j) {
        int m = j*32 + lane;
        s += cw[m] * out_b[m];
    }
    #pragma unroll
    for (int off = 16; off; off >>= 1) s += __shfl_xor_sync(0xffffffffu, s, off);
    if (lane == 0) bc[o] = s + conv1_b[o];
}

// ---------------- tf32 WMMA GEMM core: 64x64 tile, 4 warps, cp.async 2-stage
#define GBM 64
#define GBN 64
#define GBK 16
#define ALD 20
#define BLD 20
#define SLD 36
#define STG (GBM*ALD + GBN*BLD)   // 2560 floats per stage

__device__ __forceinline__
void gemm64_core(float* smem, const float* A, const float* B,
                 const float* bias, float* C, int N, int K, int relu,
                 const float* pos, const float* cam, float* out2,
                 __half* outh, int bm, int bn)
{
    int tid  = threadIdx.x;
    int w    = tid >> 5;
    int lane = tid & 31;
    int wm   = w >> 1;
    int wn   = w & 1;
    int lrow = tid >> 2;            // 0..31
    int lcol = (tid & 3) << 2;      // 0,4,8,12

    uint32_t sbase = (uint32_t)__cvta_generic_to_shared(smem);

    wmma::fragment<wmma::accumulator, 16, 16, 8, float> c[2][2];
    #pragma unroll
    for (int i = 0; i < 2; ++i)
        #pragma unroll
        for (int j = 0; j < 2; ++j) wmma::fill_fragment(c[i][j], 0.f);

    const int niter = K / GBK;

    // issue loads for stage s, k-offset k0
    #define ISSUE(s, k0) do {                                                            \
        uint32_t abase = sbase + (uint32_t)((s)*STG)*4u;                                 \
        uint32_t bbase = abase + (uint32_t)(GBM*ALD)*4u;                                 \
        cp_async16(abase + (uint32_t)(lrow*ALD + lcol)*4u,      A + (size_t)(bm + lrow)*K + (k0) + lcol);      \
        cp_async16(abase + (uint32_t)((lrow+32)*ALD + lcol)*4u, A + (size_t)(bm + lrow + 32)*K + (k0) + lcol); \
        cp_async16(bbase + (uint32_t)(lrow*BLD + lcol)*4u,      B + (size_t)(bn + lrow)*K + (k0) + lcol);      \
        cp_async16(bbase + (uint32_t)((lrow+32)*BLD + lcol)*4u, B + (size_t)(bn + lrow + 32)*K + (k0) + lcol); \
    } while (0)

    ISSUE(0, 0);
    cp_commit();

    for (int i = 0; i < niter; ++i) {
        if (i + 1 < niter) {
            ISSUE((i + 1) & 1, (i + 1) * GBK);
            cp_commit();
            cp_wait<1>();
        } else {
            cp_wait<0>();
        }
        __syncthreads();

        float* As = smem + (i & 1) * STG;
        float* Bs = As + GBM*ALD;
        #pragma unroll
        for (int kk = 0; kk < GBK; kk += 8) {
            wmma::fragment<wmma::matrix_a, 16, 16, 8, wmma::precision::tf32, wmma::row_major> a[2];
            wmma::fragment<wmma::matrix_b, 16, 16, 8, wmma::precision::tf32, wmma::col_major> b[2];
            #pragma unroll
            for (int ii = 0; ii < 2; ++ii)
                wmma::load_matrix_sync(a[ii], &As[(wm*32 + ii*16)*ALD + kk], ALD);
            #pragma unroll
            for (int jj = 0; jj < 2; ++jj)
                wmma::load_matrix_sync(b[jj], &Bs[(wn*32 + jj*16)*BLD + kk], BLD);
            #pragma unroll
            for (int ii = 0; ii < 2; ++ii)
                #pragma unroll
                for (int jj = 0; jj < 2; ++jj)
                    wmma::mma_sync(c[ii][jj], a[ii], b[jj], c[ii][jj]);
        }
        __syncthreads();
    }
    #undef ISSUE

    // epilogue via smem stage (reuse smem)
    float* ws = smem + w * (32*SLD);
    #pragma unroll
    for (int i = 0; i < 2; ++i)
        #pragma unroll
        for (int j = 0; j < 2; ++j)
            wmma::store_matrix_sync(ws + (i*16)*SLD + j*16, c[i][j], SLD, wmma::mem_row_major);
    __syncwarp();

    int r0   = lane >> 3;          // 0..3
    int col4 = (lane & 7) << 2;    // 0..28
    int ncol = bn + wn*32 + col4;
    float4 bb = *(const float4*)(bias + ncol);
    #pragma unroll
    for (int it = 0; it < 8; ++it) {
        int row = r0 + it*4;
        int m = bm + wm*32 + row;
        float4 v = *(float4*)&ws[row*SLD + col4];
        v.x += bb.x; v.y += bb.y; v.z += bb.z; v.w += bb.w;
        if (relu) { v.x = fmaxf(v.x,0.f); v.y = fmaxf(v.y,0.f); v.z = fmaxf(v.z,0.f); v.w = fmaxf(v.w,0.f); }
        if (C)
            *(float4*)(C + (size_t)m*N + ncol) = v;
        if (outh) {
            __half2* dst = (__half2*)(outh + (size_t)m*N + ncol);
            dst[0] = __floats2half2_rn(v.x, v.y);
            dst[1] = __floats2half2_rn(v.z, v.w);
        }
        if (out2) {
            int pix = m % HWW, cm = m / HWW;
            float4 p = *(const float4*)(pos + (size_t)pix*DD + ncol);
            float4 e = *(const float4*)(cam + (size_t)cm*DD + ncol);
            float4 q;
            q.x = v.x + p.x + e.x; q.y = v.y + p.y + e.y;
            q.z = v.z + p.z + e.z; q.w = v.w + p.w + e.w;
            *(float4*)(out2 + (size_t)m*N + ncol) = q;
        }
    }
}

// single GEMM
__global__ __launch_bounds__(128)
void sgemm_tc_kernel(const float* __restrict__ A, const float* __restrict__ B,
                     const float* __restrict__ bias, float* __restrict__ C,
                     int M, int N, int K, int relu,
                     const float* __restrict__ pos, const float* __restrict__ cam,
                     float* __restrict__ out2,
                     __half* __restrict__ outh)
{
    __shared__ float smem[2*STG];            // 20 KB (>= 4608 epilogue floats)
    gemm64_core(smem, A, B, bias, C, N, K, relu, pos, cam, out2, outh,
                blockIdx.y * GBM, blockIdx.x * GBN);
}

// dual GEMM: kv (N=512, fp16 out) + offsets (N=384, fp32 out) in one launch
__global__ __launch_bounds__(128)
void sgemm_dual_kernel(const float* __restrict__ srcb, const float* __restrict__ wkv,
                       const float* __restrict__ bkv, __half* __restrict__ kvh,
                       const float* __restrict__ qry, const float* __restrict__ offw,
                       const float* __restrict__ offb_bias, float* __restrict__ offb)
{
    __shared__ float smem[2*STG];
    int bx = blockIdx.x;
    if (bx < NKV/GBN) {
        gemm64_core(smem, srcb, wkv, bkv, (float*)0, NKV, DD, 0, 0, 0, 0, kvh,
                    blockIdx.y * GBM, bx * GBN);
    } else {
        gemm64_core(smem, qry, offw, offb_bias, offb, NOFF, DD, 0, 0, 0, 0, 0,
                    blockIdx.y * GBM, (bx - NKV/GBN) * GBN);
    }
}

// mean over HW per camera: two-stage
__global__ void mean_part_kernel(const float* __restrict__ qry, float* __restrict__ part)
{
    int cm = blockIdx.x, blk = blockIdx.y, c = threadIdx.x;
    int p0 = blk * 50;
    float s = 0.f;
    #pragma unroll 5
    for (int p = 0; p < 50; ++p)
        s += qry[(size_t)(cm*HWW + p0 + p)*DD + c];
    part[(size_t)(cm*16 + blk)*DD + c] = s;
}

__global__ void mean_reduce_kernel(const float* __restrict__ part, float* __restrict__ meanb)
{
    int cm = blockIdx.x, c = threadIdx.x;
    float s = 0.f;
    #pragma unroll
    for (int i = 0; i < 16; ++i) s += part[(size_t)(cm*16 + i)*DD + c];
    meanb[cm*DD + c] = s * (1.0f/(float)HWW);
}

__global__ void gtok_kernel(const float* __restrict__ meanb, const float* __restrict__ w,
                            const float* __restrict__ b, float* __restrict__ gtok)
{
    int cm = blockIdx.x, o = threadIdx.x;
    float s = b[o];
    const float* mrow = meanb + cm*DD;
    const float* wrow = w + (size_t)o*DD;
    #pragma unroll 4
    for (int c = 0; c < DD; ++c) s += mrow[c] * wrow[c];
    gtok[cm*DD + o] = s;
}

// fused deformable gather + attention over packed fp16 KV.
__global__ __launch_bounds__(256)
void attn_kernel(const float* __restrict__ qry, const __half* __restrict__ kv,
                 const float* __restrict__ offs,
                 const float* __restrict__ gtok, float* __restrict__ attn_out)
{
    int q    = blockIdx.x;
    int h    = threadIdx.y;
    int lane = threadIdx.x;
    int pix = q % HWW;
    int row = pix / WW, col = pix % WW;
    float qd = qry[(size_t)q*DD + h*HDIM + lane] * 0.17677669529663687f;

    float logit[30], vv[30];
    const float* offq = offs + (size_t)q*NOFF + h*(NCAM*NP*2);

    #pragma unroll
    for (int l = 0; l < NCAM; ++l) {
        const __half* kvb = kv + (size_t)(l*HWW)*NKV + h*64;
        float ks[NP], vs[NP];
        #pragma unroll
        for (int p = 0; p < NP; ++p) {
            float ox = offq[l*NP*2 + p*2 + 0];
            float oy = offq[l*NP*2 + p*2 + 1];
            float px = (float)col + ox;
            float py = (float)row + oy;
            float x0f = floorf(px), y0f = floorf(py);
            float fx = px - x0f, fy = py - y0f;
            int x0 = (int)x0f, y0 = (int)y0f;
            float ka = 0.f, va = 0.f;
            #pragma unroll
            for (int dy = 0; dy < 2; ++dy) {
                #pragma unroll
                for (int dx = 0; dx < 2; ++dx) {
                    int xi = x0 + dx, yi = y0 + dy;
                    if (xi >= 0 && xi < WW && yi >= 0 && yi < HH) {
                        float wgt = (dx ? fx : 1.f - fx) * (dy ? fy : 1.f - fy);
                        size_t idx = (size_t)(yi*WW + xi) * NKV;
                        ka = fmaf(wgt, __half2float(__ldg(kvb + idx + lane)), ka);
                        va = fmaf(wgt, __half2float(__ldg(kvb + idx + 32 + lane)), va);
                    }
                }
            }
            ks[p] = ka; vs[p] = va;
        }
        #pragma unroll
        for (int p = 0; p < NP; ++p) {
            float d = qd * ks[p];
            #pragma unroll
            for (int o = 16; o; o >>= 1) d += __shfl_xor_sync(0xffffffffu, d, o);
            logit[l*5 + p] = d;
            vv[l*5 + p] = vs[p];
        }
        float kg = gtok[l*DD + h*HDIM + lane];
        float d = qd * kg;
        #pragma unroll
        for (int o = 16; o; o >>= 1) d += __shfl_xor_sync(0xffffffffu, d, o);
        logit[l*5 + 4] = d;
        vv[l*5 + 4] = kg;
    }
    float m = -1e30f;
    #pragma unroll
    for (int i = 0; i < 30; ++i) m = fmaxf(m, logit[i]);
    float s = 0.f, o = 0.f;
    #pragma unroll
    for (int i = 0; i < 30; ++i) { float e = __expf(logit[i] - m); s += e; o = fmaf(e, vv[i], o); }
    attn_out[(size_t)q*DD + h*HDIM + lane] = o / s;
}

// block-wide sum over 256 threads
__device__ __forceinline__ float block_sum_256(float v, float* sh)
{
    int lane = threadIdx.x & 31, wid = threadIdx.x >> 5;
    #pragma unroll
    for (int o = 16; o; o >>= 1) v += __shfl_xor_sync(0xffffffffu, v, o);
    if (lane == 0) sh[wid] = v;
    __syncthreads();
    float t = 0.f;
    #pragma unroll
    for (int i = 0; i < 8; ++i) t += sh[i];
    __syncthreads();
    return t;
}

__global__ __launch_bounds__(256)
void ln_kernel(const float* __restrict__ A, const float* __restrict__ Bd,
               const float* __restrict__ gam, const float* __restrict__ bet,
               float* __restrict__ out)
{
    __shared__ float sh[8];
    int q = blockIdx.x, c = threadIdx.x;
    float v = A[(size_t)q*DD + c] + Bd[(size_t)q*DD + c];
    float mu = block_sum_256(v, sh) * (1.f/(float)DD);
    float d = v - mu;
    float var = block_sum_256(d*d, sh) * (1.f/(float)DD);
    out[(size_t)q*DD + c] = d * rsqrtf(var + 1e-5f) * gam[c] + bet[c];
}

__global__ __launch_bounds__(256)
void ln_out_kernel(const float* __restrict__ A, const float* __restrict__ Bd,
                   const float* __restrict__ gam, const float* __restrict__ bet,
                   float* __restrict__ out)
{
    __shared__ float sh[8];
    int q = blockIdx.x, c = threadIdx.x;
    float v = A[(size_t)q*DD + c] + Bd[(size_t)q*DD + c];
    float mu = block_sum_256(v, sh) * (1.f/(float)DD);
    float d = v - mu;
    float var = block_sum_256(d*d, sh) * (1.f/(float)DD);
    float r = d * rsqrtf(var + 1e-5f) * gam[c] + bet[c];
    int cm = q / HWW, pix = q % HWW;
    out[(size_t)(cm*DD + c)*HWW + pix] = r;
}

// ------------------------- launch ------------------------------------------
extern "C" void kernel_launch(void* const* d_in, const int* in_sizes, int n_in,
                              void* d_out, int out_size)
{
    const float* x       = (const float*)d_in[0];
    const float* conv0_w = (const float*)d_in[1];
    const float* conv0_b = (const float*)d_in[2];
    const float* conv2_w = (const float*)d_in[3];
    const float* conv2_b = (const float*)d_in[4];
    const float* cam_emb = (const float*)d_in[5];
    const float* off_w   = (const float*)d_in[6];
    const float* off_b   = (const float*)d_in[7];
    const float* val_w   = (const float*)d_in[8];
    const float* val_b   = (const float*)d_in[9];
    const float* key_w   = (const float*)d_in[10];
    const float* key_b   = (const float*)d_in[11];
    const float* out_w   = (const float*)d_in[12];
    const float* out_b   = (const float*)d_in[13];
    const float* conv1_w = (const float*)d_in[14];
    const float* conv1_b = (const float*)d_in[15];
    const float* norm0_g = (const float*)d_in[16];
    const float* norm0_b = (const float*)d_in[17];
    const float* lin1_w  = (const float*)d_in[18];
    const float* lin1_b  = (const float*)d_in[19];
    const float* lin2_w  = (const float*)d_in[20];
    const float* lin2_b  = (const float*)d_in[21];
    const float* norm2_g = (const float*)d_in[22];
    const float* norm2_b = (const float*)d_in[23];

    float *res, *srcb, *qry, *offb, *posb, *part, *meanb, *gtokb,
          *attb, *t1, *t2, *lnb, *wc, *bc, *wkv, *bkv;
    __half *kvh;
    cudaGetSymbolAddress((void**)&res,   g_res);
    cudaGetSymbolAddress((void**)&srcb,  g_srcb);
    cudaGetSymbolAddress((void**)&qry,   g_qry);
    cudaGetSymbolAddress((void**)&kvh,   g_kvh);
    cudaGetSymbolAddress((void**)&offb,  g_offb);
    cudaGetSymbolAddress((void**)&posb,  g_posb);
    cudaGetSymbolAddress((void**)&part,  g_part);
    cudaGetSymbolAddress((void**)&meanb, g_meanb);
    cudaGetSymbolAddress((void**)&gtokb, g_gtokb);
    cudaGetSymbolAddress((void**)&attb,  g_attb);
    cudaGetSymbolAddress((void**)&t1,    g_t1b);
    cudaGetSymbolAddress((void**)&t2,    g_t2b);
    cudaGetSymbolAddress((void**)&lnb,   g_lnb);
    cudaGetSymbolAddress((void**)&wc,    g_wc);
    cudaGetSymbolAddress((void**)&bc,    g_bc);
    cudaGetSymbolAddress((void**)&wkv,   g_wkv);
    cudaGetSymbolAddress((void**)&bkv,   g_bkv);

    dim3 tb(32, 8);
    const int MB = LQ / GBM;   // 75

    // launches 0-2: prep (so launch index 3 = conv0 GEMM stays in profiled slot)
    pack_kvw_kernel<<<NKV, DD>>>(key_w, val_w, key_b, val_b, wkv, bkv);
    pos_kernel<<<HWW, DD>>>(posb);
    transpose_in_kernel<<<dim3(25, 8, NCAM), tb>>>(x, res);

    // launch 3: conv0 + fused (pos + cam_emb) second output  << profiled slot
    sgemm_tc_kernel<<<dim3(DD/GBN, MB), 128>>>(res, conv0_w, conv0_b, srcb, LQ, DD, DD, 0,
                                               posb, cam_emb, qry, 0);

    // merged kv (N=512 -> fp16 KV) + offsets (N=384) GEMM, 1050 blocks
    sgemm_dual_kernel<<<dim3(NKV/GBN + NOFF/GBN, MB), 128>>>(srcb, wkv, bkv, kvh,
                                                             qry, off_w, off_b, offb);

    // g-token path
    mean_part_kernel<<<dim3(NCAM,16), DD>>>(qry, part);
    mean_reduce_kernel<<<NCAM, DD>>>(part, meanb);
    gtok_kernel<<<NCAM, DD>>>(meanb, conv2_w, conv2_b, gtokb);

    // fused gather + attention
    attn_kernel<<<LQ, tb>>>(qry, kvh, offb, gtokb, attb);

    // weight folding
    fold_w_kernel<<<dim3(4,4), 256>>>(conv1_w, out_w, wc);
    fold_b_kernel<<<32, 256>>>(conv1_w, out_b, conv1_b, bc);

    // combined out_w+conv1 projection
    sgemm_tc_kernel<<<dim3(DD/GBN, MB), 128>>>(attb, wc, bc, t2, LQ, DD, DD, 0, 0, 0, 0, 0);

    ln_kernel<<<LQ, DD>>>(res, t2, norm0_g, norm0_b, lnb);

    sgemm_tc_kernel<<<dim3(DD/GBN, MB), 128>>>(lnb, lin1_w, lin1_b, t1, LQ, DD, DD, 1, 0, 0, 0, 0);
    sgemm_tc_kernel<<<dim3(DD/GBN, MB), 128>>>(t1, lin2_w, lin2_b, t2, LQ, DD, DD, 0, 0, 0, 0, 0);

    ln_out_kernel<<<LQ, DD>>>(lnb, t2, norm2_g, norm2_b, (float*)d_out);
}

// round 12
// speedup vs baseline: 1.0832x; 1.0832x over previous
#include <cuda_runtime.h>
#include <cuda_fp16.h>
#include <mma.h>
#include <math.h>
#include <stdint.h>

using namespace nvcuda;

#define NCAM 6
#define NH   8
#define NP   4
#define DD   256
#define HH   20
#define WW   40
#define HWW  800
#define LQ   4800
#define HDIM 32
#define NOFF 384
#define NKV  512
#define TWO_PI 6.283185307179586f

// ------------------------- scratch (static device arrays) -------------------
__device__ float  g_res  [LQ*DD];
__device__ float  g_srcb [LQ*DD];
__device__ float  g_qry  [LQ*DD];
__device__ __half g_kvh  [(size_t)LQ*NKV];
__device__ float  g_offb [LQ*NOFF];
__device__ float  g_posb [HWW*DD];
__device__ float  g_part [NCAM*16*DD];
__device__ float  g_meanb[NCAM*DD];
__device__ float  g_gtokb[NCAM*DD];
__device__ float  g_attb [LQ*DD];
__device__ float  g_t1b  [LQ*DD];
__device__ float  g_t2b  [LQ*DD];
__device__ float  g_lnb  [LQ*DD];
__device__ float  g_wc   [DD*DD];
__device__ float  g_bc   [DD];
__device__ float  g_wkv  [NKV*DD];
__device__ float  g_bkv  [NKV];

// ------------------------- small prep kernels -------------------------------

__global__ void pack_kvw_kernel(const float* __restrict__ key_w, const float* __restrict__ val_w,
                                const float* __restrict__ key_b, const float* __restrict__ val_b,
                                float* __restrict__ wkv, float* __restrict__ bkv)
{
    int n = blockIdx.x;
    int c = threadIdx.x;
    int head = n >> 6, ch = n & 63;
    const float* src = (ch < 32) ? (key_w + (size_t)(head*32 + ch)*DD)
                                 : (val_w + (size_t)(head*32 + ch - 32)*DD);
    wkv[(size_t)n*DD + c] = src[c];
    if (c == 0)
        bkv[n] = (ch < 32) ? key_b[head*32 + ch] : val_b[head*32 + ch - 32];
}

__global__ void transpose_in_kernel(const float* __restrict__ x, float* __restrict__ res)
{
    __shared__ float tile[32][33];
    int cam = blockIdx.z;
    int c0  = blockIdx.y * 32;
    int p0  = blockIdx.x * 32;
    int tx = threadIdx.x, ty = threadIdx.y;
    #pragma unroll
    for (int i = ty; i < 32; i += 8)
        tile[i][tx] = x[(size_t)(cam*DD + c0 + i)*HWW + p0 + tx];
    __syncthreads();
    #pragma unroll
    for (int i = ty; i < 32; i += 8)
        res[(size_t)(cam*HWW + p0 + i)*DD + c0 + tx] = tile[tx][i];
}

__global__ void pos_kernel(float* __restrict__ pos)
{
    int pix = blockIdx.x;
    int c   = threadIdx.x;
    int i = pix / WW, j = pix % WW;
    float v; int cc;
    if (c < 128) { v = (float)(i + 1) / (20.0f + 1e-6f) * TWO_PI; cc = c; }
    else         { v = (float)(j + 1) / (40.0f + 1e-6f) * TWO_PI; cc = c - 128; }
    float expo = (2.0f * (float)(cc / 2)) / 128.0f;
    float dt = powf(10000.0f, expo);
    float ph = v / dt;
    pos[(size_t)pix*DD + c] = (cc & 1) ? cosf(ph) : sinf(ph);
}

// Wc = conv1_w @ out_w  (NN gemm, 256x256x256)
__global__ __launch_bounds__(256)
void fold_w_kernel(const float* __restrict__ A, const float* __restrict__ B,
                   float* __restrict__ C)
{
    __shared__ float As[16][68];
    __shared__ float Bs[16][68];
    int tid = threadIdx.x;
    int bm = blockIdx.y * 64, bn = blockIdx.x * 64;
    int ra = tid >> 2;
    int ca = (tid & 3) << 2;
    int br = tid >> 4;
    int bcol = (tid & 15) << 2;
    int tr = (tid >> 4) << 2;
    int tc = (tid & 15) << 2;

    float acc[4][4];
    #pragma unroll
    for (int i = 0; i < 4; ++i)
        #pragma unroll
        for (int j = 0; j < 4; ++j) acc[i][j] = 0.f;

    for (int k0 = 0; k0 < DD; k0 += 16) {
        float4 a = *(const float4*)(A + (size_t)(bm + ra)*DD + k0 + ca);
        As[ca+0][ra] = a.x; As[ca+1][ra] = a.y; As[ca+2][ra] = a.z; As[ca+3][ra] = a.w;
        float4 b = *(const float4*)(B + (size_t)(k0 + br)*DD + bn + bcol);
        *(float4*)&Bs[br][bcol] = b;
        __syncthreads();
        #pragma unroll
        for (int kk = 0; kk < 16; ++kk) {
            float4 av = *(const float4*)&As[kk][tr];
            float4 bv = *(const float4*)&Bs[kk][tc];
            float ar[4] = {av.x, av.y, av.z, av.w};
            float br2[4] = {bv.x, bv.y, bv.z, bv.w};
            #pragma unroll
            for (int i = 0; i < 4; ++i)
                #pragma unroll
                for (int j = 0; j < 4; ++j) acc[i][j] = fmaf(ar[i], br2[j], acc[i][j]);
        }
        __syncthreads();
    }
    #pragma unroll
    for (int i = 0; i < 4; ++i)
        *(float4*)(C + (size_t)(bm + tr + i)*DD + bn + tc) = *(float4*)acc[i];
}

__global__ void fold_b_kernel(const float* __restrict__ conv1_w, const float* __restrict__ out_b,
                              const float* __restrict__ conv1_b, float* __restrict__ bc)
{
    int w = threadIdx.x >> 5, lane = threadIdx.x & 31;
    int o = blockIdx.x * 8 + w;
    const float* cw = conv1_w + (size_t)o*DD;
    float s = 0.f;
    #pragma unroll
    for (int j = 0; j < 8; ++j) {
        int m = j*32 + lane;
        s += cw[m] * out_b[m];
    }
    #pragma unroll
    for (int off = 16; off; off >>= 1) s += __shfl_xor_sync(0xffffffffu, s, off);
    if (lane == 0) bc[o] = s + conv1_b[o];
}

// ---------------- tf32 WMMA GEMM core (round-9 single-buffer version) -------
// C[M,N] = A[M,K] B[N,K]^T + bias. 64x64 tile, 4 warps (2x2), 32x32/warp.
#define GBM 64
#define GBN 64
#define GBK 16
#define ALD 20
#define BLD 20
#define SLD 36

__device__ __forceinline__
void gemm64_core(float* smem, const float* A, const float* B,
                 const float* bias, float* C, int N, int K, int relu,
                 const float* pos, const float* cam, float* out2,
                 __half* outh, int bm, int bn)
{
    float* As = smem;                        // [64][20] = 1280
    float* Bs = smem + 1280;                 // [64][20] = 1280

    int tid  = threadIdx.x;
    int w    = tid >> 5;
    int lane = tid & 31;
    int wm   = w >> 1;
    int wn   = w & 1;
    int lrow = tid >> 2;            // 0..31
    int lcol = (tid & 3) << 2;      // 0,4,8,12

    wmma::fragment<wmma::accumulator, 16, 16, 8, float> c[2][2];
    #pragma unroll
    for (int i = 0; i < 2; ++i)
        #pragma unroll
        for (int j = 0; j < 2; ++j) wmma::fill_fragment(c[i][j], 0.f);

    for (int k0 = 0; k0 < K; k0 += GBK) {
        {
            float4 a = *(const float4*)(A + (size_t)(bm + lrow)*K + k0 + lcol);
            As[lrow*ALD + lcol+0] = wmma::__float_to_tf32(a.x);
            As[lrow*ALD + lcol+1] = wmma::__float_to_tf32(a.y);
            As[lrow*ALD + lcol+2] = wmma::__float_to_tf32(a.z);
            As[lrow*ALD + lcol+3] = wmma::__float_to_tf32(a.w);
            a = *(const float4*)(A + (size_t)(bm + lrow + 32)*K + k0 + lcol);
            As[(lrow+32)*ALD + lcol+0] = wmma::__float_to_tf32(a.x);
            As[(lrow+32)*ALD + lcol+1] = wmma::__float_to_tf32(a.y);
            As[(lrow+32)*ALD + lcol+2] = wmma::__float_to_tf32(a.z);
            As[(lrow+32)*ALD + lcol+3] = wmma::__float_to_tf32(a.w);
        }
        {
            float4 b = *(const float4*)(B + (size_t)(bn + lrow)*K + k0 + lcol);
            Bs[lrow*BLD + lcol+0] = wmma::__float_to_tf32(b.x);
            Bs[lrow*BLD + lcol+1] = wmma::__float_to_tf32(b.y);
            Bs[lrow*BLD + lcol+2] = wmma::__float_to_tf32(b.z);
            Bs[lrow*BLD + lcol+3] = wmma::__float_to_tf32(b.w);
            b = *(const float4*)(B + (size_t)(bn + lrow + 32)*K + k0 + lcol);
            Bs[(lrow+32)*BLD + lcol+0] = wmma::__float_to_tf32(b.x);
            Bs[(lrow+32)*BLD + lcol+1] = wmma::__float_to_tf32(b.y);
            Bs[(lrow+32)*BLD + lcol+2] = wmma::__float_to_tf32(b.z);
            Bs[(lrow+32)*BLD + lcol+3] = wmma::__float_to_tf32(b.w);
        }
        __syncthreads();

        #pragma unroll
        for (int kk = 0; kk < GBK; kk += 8) {
            wmma::fragment<wmma::matrix_a, 16, 16, 8, wmma::precision::tf32, wmma::row_major> a[2];
            wmma::fragment<wmma::matrix_b, 16, 16, 8, wmma::precision::tf32, wmma::col_major> b[2];
            #pragma unroll
            for (int ii = 0; ii < 2; ++ii)
                wmma::load_matrix_sync(a[ii], &As[(wm*32 + ii*16)*ALD + kk], ALD);
            #pragma unroll
            for (int jj = 0; jj < 2; ++jj)
                wmma::load_matrix_sync(b[jj], &Bs[(wn*32 + jj*16)*BLD + kk], BLD);
            #pragma unroll
            for (int ii = 0; ii < 2; ++ii)
                #pragma unroll
                for (int jj = 0; jj < 2; ++jj)
                    wmma::mma_sync(c[ii][jj], a[ii], b[jj], c[ii][jj]);
        }
        __syncthreads();
    }

    // epilogue via smem stage (reuse smem)
    float* ws = smem + w * (32*SLD);
    #pragma unroll
    for (int i = 0; i < 2; ++i)
        #pragma unroll
        for (int j = 0; j < 2; ++j)
            wmma::store_matrix_sync(ws + (i*16)*SLD + j*16, c[i][j], SLD, wmma::mem_row_major);
    __syncwarp();

    int r0   = lane >> 3;          // 0..3
    int col4 = (lane & 7) << 2;    // 0..28
    int ncol = bn + wn*32 + col4;
    float4 bb = *(const float4*)(bias + ncol);
    #pragma unroll
    for (int it = 0; it < 8; ++it) {
        int row = r0 + it*4;
        int m = bm + wm*32 + row;
        float4 v = *(float4*)&ws[row*SLD + col4];
        v.x += bb.x; v.y += bb.y; v.z += bb.z; v.w += bb.w;
        if (relu) { v.x = fmaxf(v.x,0.f); v.y = fmaxf(v.y,0.f); v.z = fmaxf(v.z,0.f); v.w = fmaxf(v.w,0.f); }
        if (C)
            *(float4*)(C + (size_t)m*N + ncol) = v;
        if (outh) {
            __half2* dst = (__half2*)(outh + (size_t)m*N + ncol);
            dst[0] = __floats2half2_rn(v.x, v.y);
            dst[1] = __floats2half2_rn(v.z, v.w);
        }
        if (out2) {
            int pix = m % HWW, cm = m / HWW;
            float4 p = *(const float4*)(pos + (size_t)pix*DD + ncol);
            float4 e = *(const float4*)(cam + (size_t)cm*DD + ncol);
            float4 q;
            q.x = v.x + p.x + e.x; q.y = v.y + p.y + e.y;
            q.z = v.z + p.z + e.z; q.w = v.w + p.w + e.w;
            *(float4*)(out2 + (size_t)m*N + ncol) = q;
        }
    }
}

// single GEMM
__global__ __launch_bounds__(128)
void sgemm_tc_kernel(const float* __restrict__ A, const float* __restrict__ B,
                     const float* __restrict__ bias, float* __restrict__ C,
                     int M, int N, int K, int relu,
                     const float* __restrict__ pos, const float* __restrict__ cam,
                     float* __restrict__ out2,
                     __half* __restrict__ outh)
{
    __shared__ float smem[4608];
    gemm64_core(smem, A, B, bias, C, N, K, relu, pos, cam, out2, outh,
                blockIdx.y * GBM, blockIdx.x * GBN);
}

// dual GEMM: kv (N=512, fp16 out) + offsets (N=384, fp32 out) in one launch
__global__ __launch_bounds__(128)
void sgemm_dual_kernel(const float* __restrict__ srcb, const float* __restrict__ wkv,
                       const float* __restrict__ bkv, __half* __restrict__ kvh,
                       const float* __restrict__ qry, const float* __restrict__ offw,
                       const float* __restrict__ offb_bias, float* __restrict__ offb)
{
    __shared__ float smem[4608];
    int bx = blockIdx.x;
    if (bx < NKV/GBN) {
        gemm64_core(smem, srcb, wkv, bkv, (float*)0, NKV, DD, 0, 0, 0, 0, kvh,
                    blockIdx.y * GBM, bx * GBN);
    } else {
        gemm64_core(smem, qry, offw, offb_bias, offb, NOFF, DD, 0, 0, 0, 0, 0,
                    blockIdx.y * GBM, (bx - NKV/GBN) * GBN);
    }
}

// mean over HW per camera: two-stage
__global__ void mean_part_kernel(const float* __restrict__ qry, float* __restrict__ part)
{
    int cm = blockIdx.x, blk = blockIdx.y, c = threadIdx.x;
    int p0 = blk * 50;
    float s = 0.f;
    #pragma unroll 5
    for (int p = 0; p < 50; ++p)
        s += qry[(size_t)(cm*HWW + p0 + p)*DD + c];
    part[(size_t)(cm*16 + blk)*DD + c] = s;
}

__global__ void mean_reduce_kernel(const float* __restrict__ part, float* __restrict__ meanb)
{
    int cm = blockIdx.x, c = threadIdx.x;
    float s = 0.f;
    #pragma unroll
    for (int i = 0; i < 16; ++i) s += part[(size_t)(cm*16 + i)*DD + c];
    meanb[cm*DD + c] = s * (1.0f/(float)HWW);
}

__global__ void gtok_kernel(const float* __restrict__ meanb, const float* __restrict__ w,
                            const float* __restrict__ b, float* __restrict__ gtok)
{
    int cm = blockIdx.x, o = threadIdx.x;
    float s = b[o];
    const float* mrow = meanb + cm*DD;
    const float* wrow = w + (size_t)o*DD;
    #pragma unroll 4
    for (int c = 0; c < DD; ++c) s += mrow[c] * wrow[c];
    gtok[cm*DD + o] = s;
}

// fused deformable gather + attention over packed fp16 KV.
__global__ __launch_bounds__(256)
void attn_kernel(const float* __restrict__ qry, const __half* __restrict__ kv,
                 const float* __restrict__ offs,
                 const float* __restrict__ gtok, float* __restrict__ attn_out)
{
    int q    = blockIdx.x;
    int h    = threadIdx.y;
    int lane = threadIdx.x;
    int pix = q % HWW;
    int row = pix / WW, col = pix % WW;
    float qd = qry[(size_t)q*DD + h*HDIM + lane] * 0.17677669529663687f;

    float logit[30], vv[30];
    const float* offq = offs + (size_t)q*NOFF + h*(NCAM*NP*2);

    #pragma unroll
    for (int l = 0; l < NCAM; ++l) {
        const __half* kvb = kv + (size_t)(l*HWW)*NKV + h*64;
        float ks[NP], vs[NP];
        #pragma unroll
        for (int p = 0; p < NP; ++p) {
            float ox = offq[l*NP*2 + p*2 + 0];
            float oy = offq[l*NP*2 + p*2 + 1];
            float px = (float)col + ox;
            float py = (float)row + oy;
            float x0f = floorf(px), y0f = floorf(py);
            float fx = px - x0f, fy = py - y0f;
            int x0 = (int)x0f, y0 = (int)y0f;
            float ka = 0.f, va = 0.f;
            #pragma unroll
            for (int dy = 0; dy < 2; ++dy) {
                #pragma unroll
                for (int dx = 0; dx < 2; ++dx) {
                    int xi = x0 + dx, yi = y0 + dy;
                    if (xi >= 0 && xi < WW && yi >= 0 && yi < HH) {
                        float wgt = (dx ? fx : 1.f - fx) * (dy ? fy : 1.f - fy);
                        size_t idx = (size_t)(yi*WW + xi) * NKV;
                        ka = fmaf(wgt, __half2float(__ldg(kvb + idx + lane)), ka);
                        va = fmaf(wgt, __half2float(__ldg(kvb + idx + 32 + lane)), va);
                    }
                }
            }
            ks[p] = ka; vs[p] = va;
        }
        #pragma unroll
        for (int p = 0; p < NP; ++p) {
            float d = qd * ks[p];
            #pragma unroll
            for (int o = 16; o; o >>= 1) d += __shfl_xor_sync(0xffffffffu, d, o);
            logit[l*5 + p] = d;
            vv[l*5 + p] = vs[p];
        }
        float kg = gtok[l*DD + h*HDIM + lane];
        float d = qd * kg;
        #pragma unroll
        for (int o = 16; o; o >>= 1) d += __shfl_xor_sync(0xffffffffu, d, o);
        logit[l*5 + 4] = d;
        vv[l*5 + 4] = kg;
    }
    float m = -1e30f;
    #pragma unroll
    for (int i = 0; i < 30; ++i) m = fmaxf(m, logit[i]);
    float s = 0.f, o = 0.f;
    #pragma unroll
    for (int i = 0; i < 30; ++i) { float e = __expf(logit[i] - m); s += e; o = fmaf(e, vv[i], o); }
    attn_out[(size_t)q*DD + h*HDIM + lane] = o / s;
}

// block-wide sum over 256 threads
__device__ __forceinline__ float block_sum_256(float v, float* sh)
{
    int lane = threadIdx.x & 31, wid = threadIdx.x >> 5;
    #pragma unroll
    for (int o = 16; o; o >>= 1) v += __shfl_xor_sync(0xffffffffu, v, o);
    if (lane == 0) sh[wid] = v;
    __syncthreads();
    float t = 0.f;
    #pragma unroll
    for (int i = 0; i < 8; ++i) t += sh[i];
    __syncthreads();
    return t;
}

__global__ __launch_bounds__(256)
void ln_kernel(const float* __restrict__ A, const float* __restrict__ Bd,
               const float* __restrict__ gam, const float* __restrict__ bet,
               float* __restrict__ out)
{
    __shared__ float sh[8];
    int q = blockIdx.x, c = threadIdx.x;
    float v = A[(size_t)q*DD + c] + Bd[(size_t)q*DD + c];
    float mu = block_sum_256(v, sh) * (1.f/(float)DD);
    float d = v - mu;
    float var = block_sum_256(d*d, sh) * (1.f/(float)DD);
    out[(size_t)q*DD + c] = d * rsqrtf(var + 1e-5f) * gam[c] + bet[c];
}

__global__ __launch_bounds__(256)
void ln_out_kernel(const float* __restrict__ A, const float* __restrict__ Bd,
                   const float* __restrict__ gam, const float* __restrict__ bet,
                   float* __restrict__ out)
{
    __shared__ float sh[8];
    int q = blockIdx.x, c = threadIdx.x;
    float v = A[(size_t)q*DD + c] + Bd[(size_t)q*DD + c];
    float mu = block_sum_256(v, sh) * (1.f/(float)DD);
    float d = v - mu;
    float var = block_sum_256(d*d, sh) * (1.f/(float)DD);
    float r = d * rsqrtf(var + 1e-5f) * gam[c] + bet[c];
    int cm = q / HWW, pix = q % HWW;
    out[(size_t)(cm*DD + c)*HWW + pix] = r;
}

// ------------------------- launch ------------------------------------------
extern "C" void kernel_launch(void* const* d_in, const int* in_sizes, int n_in,
                              void* d_out, int out_size)
{
    const float* x       = (const float*)d_in[0];
    const float* conv0_w = (const float*)d_in[1];
    const float* conv0_b = (const float*)d_in[2];
    const float* conv2_w = (const float*)d_in[3];
    const float* conv2_b = (const float*)d_in[4];
    const float* cam_emb = (const float*)d_in[5];
    const float* off_w   = (const float*)d_in[6];
    const float* off_b   = (const float*)d_in[7];
    const float* val_w   = (const float*)d_in[8];
    const float* val_b   = (const float*)d_in[9];
    const float* key_w   = (const float*)d_in[10];
    const float* key_b   = (const float*)d_in[11];
    const float* out_w   = (const float*)d_in[12];
    const float* out_b   = (const float*)d_in[13];
    const float* conv1_w = (const float*)d_in[14];
    const float* conv1_b = (const float*)d_in[15];
    const float* norm0_g = (const float*)d_in[16];
    const float* norm0_b = (const float*)d_in[17];
    const float* lin1_w  = (const float*)d_in[18];
    const float* lin1_b  = (const float*)d_in[19];
    const float* lin2_w  = (const float*)d_in[20];
    const float* lin2_b  = (const float*)d_in[21];
    const float* norm2_g = (const float*)d_in[22];
    const float* norm2_b = (const float*)d_in[23];

    float *res, *srcb, *qry, *offb, *posb, *part, *meanb, *gtokb,
          *attb, *t1, *t2, *lnb, *wc, *bc, *wkv, *bkv;
    __half *kvh;
    cudaGetSymbolAddress((void**)&res,   g_res);
    cudaGetSymbolAddress((void**)&srcb,  g_srcb);
    cudaGetSymbolAddress((void**)&qry,   g_qry);
    cudaGetSymbolAddress((void**)&kvh,   g_kvh);
    cudaGetSymbolAddress((void**)&offb,  g_offb);
    cudaGetSymbolAddress((void**)&posb,  g_posb);
    cudaGetSymbolAddress((void**)&part,  g_part);
    cudaGetSymbolAddress((void**)&meanb, g_meanb);
    cudaGetSymbolAddress((void**)&gtokb, g_gtokb);
    cudaGetSymbolAddress((void**)&attb,  g_attb);
    cudaGetSymbolAddress((void**)&t1,    g_t1b);
    cudaGetSymbolAddress((void**)&t2,    g_t2b);
    cudaGetSymbolAddress((void**)&lnb,   g_lnb);
    cudaGetSymbolAddress((void**)&wc,    g_wc);
    cudaGetSymbolAddress((void**)&bc,    g_bc);
    cudaGetSymbolAddress((void**)&wkv,   g_wkv);
    cudaGetSymbolAddress((void**)&bkv,   g_bkv);

    dim3 tb(32, 8);
    const int MB = LQ / GBM;   // 75

    // launches 0-2: prep (so launch index 3 = conv0 GEMM stays in profiled slot)
    pack_kvw_kernel<<<NKV, DD>>>(key_w, val_w, key_b, val_b, wkv, bkv);
    pos_kernel<<<HWW, DD>>>(posb);
    transpose_in_kernel<<<dim3(25, 8, NCAM), tb>>>(x, res);

    // launch 3: conv0 + fused (pos + cam_emb) second output  << profiled slot
    sgemm_tc_kernel<<<dim3(DD/GBN, MB), 128>>>(res, conv0_w, conv0_b, srcb, LQ, DD, DD, 0,
                                               posb, cam_emb, qry, 0);

    // merged kv (N=512 -> fp16 KV) + offsets (N=384) GEMM, 1050 blocks
    sgemm_dual_kernel<<<dim3(NKV/GBN + NOFF/GBN, MB), 128>>>(srcb, wkv, bkv, kvh,
                                                             qry, off_w, off_b, offb);

    // g-token path
    mean_part_kernel<<<dim3(NCAM,16), DD>>>(qry, part);
    mean_reduce_kernel<<<NCAM, DD>>>(part, meanb);
    gtok_kernel<<<NCAM, DD>>>(meanb, conv2_w, conv2_b, gtokb);

    // fused gather + attention
    attn_kernel<<<LQ, tb>>>(qry, kvh, offb, gtokb, attb);

    // weight folding
    fold_w_kernel<<<dim3(4,4), 256>>>(conv1_w, out_w, wc);
    fold_b_kernel<<<32, 256>>>(conv1_w, out_b, conv1_b, bc);

    // combined out_w+conv1 projection
    sgemm_tc_kernel<<<dim3(DD/GBN, MB), 128>>>(attb, wc, bc, t2, LQ, DD, DD, 0, 0, 0, 0, 0);

    ln_kernel<<<LQ, DD>>>(res, t2, norm0_g, norm0_b, lnb);

    sgemm_tc_kernel<<<dim3(DD/GBN, MB), 128>>>(lnb, lin1_w, lin1_b, t1, LQ, DD, DD, 1, 0, 0, 0, 0);
    sgemm_tc_kernel<<<dim3(DD/GBN, MB), 128>>>(t1, lin2_w, lin2_b, t2, LQ, DD, DD, 0, 0, 0, 0, 0);

    ln_out_kernel<<<LQ, DD>>>(lnb, t2, norm2_g, norm2_b, (float*)d_out);
}

// round 13
// speedup vs baseline: 1.7348x; 1.6015x over previous
#include <cuda_runtime.h>
#include <cuda_fp16.h>
#include <mma.h>
#include <math.h>
#include <stdint.h>

using namespace nvcuda;

#define NCAM 6
#define NH   8
#define NP   4
#define DD   256
#define HH   20
#define WW   40
#define HWW  800
#define LQ   4800
#define HDIM 32
#define NOFF 384
#define NKV  512
#define TWO_PI 6.283185307179586f

// ------------------------- scratch (static device arrays) -------------------
__device__ float  g_res  [LQ*DD];
__device__ float  g_srcb [LQ*DD];
__device__ float  g_qry  [LQ*DD];
__device__ __half g_kvh  [(size_t)LQ*NKV];   // interleaved (k,v) per channel
__device__ float  g_offb [LQ*NOFF];
__device__ float  g_posb [HWW*DD];
__device__ float  g_part [NCAM*16*DD];
__device__ float  g_meanb[NCAM*DD];
__device__ float  g_gtokb[NCAM*DD];
__device__ float  g_attb [LQ*DD];
__device__ float  g_t1b  [LQ*DD];
__device__ float  g_t2b  [LQ*DD];
__device__ float  g_lnb  [LQ*DD];
__device__ float  g_wc   [DD*DD];
__device__ float  g_bc   [DD];
__device__ float  g_wkv  [NKV*DD];
__device__ float  g_bkv  [NKV];

// ------------------------- small prep kernels -------------------------------

// interleave key/val weights: GEMM output column n -> (head, ch, which)
// n = head*64 + ch*2 + which   (which=0 -> key, 1 -> val)
__global__ void pack_kvw_kernel(const float* __restrict__ key_w, const float* __restrict__ val_w,
                                const float* __restrict__ key_b, const float* __restrict__ val_b,
                                float* __restrict__ wkv, float* __restrict__ bkv)
{
    int n = blockIdx.x;
    int c = threadIdx.x;
    int head  = n >> 6;
    int ch    = (n & 63) >> 1;
    int which = n & 1;
    const float* src = which ? (val_w + (size_t)(head*32 + ch)*DD)
                             : (key_w + (size_t)(head*32 + ch)*DD);
    wkv[(size_t)n*DD + c] = src[c];
    if (c == 0)
        bkv[n] = which ? val_b[head*32 + ch] : key_b[head*32 + ch];
}

__global__ void transpose_in_kernel(const float* __restrict__ x, float* __restrict__ res)
{
    __shared__ float tile[32][33];
    int cam = blockIdx.z;
    int c0  = blockIdx.y * 32;
    int p0  = blockIdx.x * 32;
    int tx = threadIdx.x, ty = threadIdx.y;
    #pragma unroll
    for (int i = ty; i < 32; i += 8)
        tile[i][tx] = x[(size_t)(cam*DD + c0 + i)*HWW + p0 + tx];
    __syncthreads();
    #pragma unroll
    for (int i = ty; i < 32; i += 8)
        res[(size_t)(cam*HWW + p0 + i)*DD + c0 + tx] = tile[tx][i];
}

__global__ void pos_kernel(float* __restrict__ pos)
{
    int pix = blockIdx.x;
    int c   = threadIdx.x;
    int i = pix / WW, j = pix % WW;
    float v; int cc;
    if (c < 128) { v = (float)(i + 1) / (20.0f + 1e-6f) * TWO_PI; cc = c; }
    else         { v = (float)(j + 1) / (40.0f + 1e-6f) * TWO_PI; cc = c - 128; }
    float expo = (2.0f * (float)(cc / 2)) / 128.0f;
    float dt = powf(10000.0f, expo);
    float ph = v / dt;
    pos[(size_t)pix*DD + c] = (cc & 1) ? cosf(ph) : sinf(ph);
}

// Wc = conv1_w @ out_w  (NN gemm, 256x256x256)
__global__ __launch_bounds__(256)
void fold_w_kernel(const float* __restrict__ A, const float* __restrict__ B,
                   float* __restrict__ C)
{
    __shared__ float As[16][68];
    __shared__ float Bs[16][68];
    int tid = threadIdx.x;
    int bm = blockIdx.y * 64, bn = blockIdx.x * 64;
    int ra = tid >> 2;
    int ca = (tid & 3) << 2;
    int br = tid >> 4;
    int bcol = (tid & 15) << 2;
    int tr = (tid >> 4) << 2;
    int tc = (tid & 15) << 2;

    float acc[4][4];
    #pragma unroll
    for (int i = 0; i < 4; ++i)
        #pragma unroll
        for (int j = 0; j < 4; ++j) acc[i][j] = 0.f;

    for (int k0 = 0; k0 < DD; k0 += 16) {
        float4 a = *(const float4*)(A + (size_t)(bm + ra)*DD + k0 + ca);
        As[ca+0][ra] = a.x; As[ca+1][ra] = a.y; As[ca+2][ra] = a.z; As[ca+3][ra] = a.w;
        float4 b = *(const float4*)(B + (size_t)(k0 + br)*DD + bn + bcol);
        *(float4*)&Bs[br][bcol] = b;
        __syncthreads();
        #pragma unroll
        for (int kk = 0; kk < 16; ++kk) {
            float4 av = *(const float4*)&As[kk][tr];
            float4 bv = *(const float4*)&Bs[kk][tc];
            float ar[4] = {av.x, av.y, av.z, av.w};
            float br2[4] = {bv.x, bv.y, bv.z, bv.w};
            #pragma unroll
            for (int i = 0; i < 4; ++i)
                #pragma unroll
                for (int j = 0; j < 4; ++j) acc[i][j] = fmaf(ar[i], br2[j], acc[i][j]);
        }
        __syncthreads();
    }
    #pragma unroll
    for (int i = 0; i < 4; ++i)
        *(float4*)(C + (size_t)(bm + tr + i)*DD + bn + tc) = *(float4*)acc[i];
}

__global__ void fold_b_kernel(const float* __restrict__ conv1_w, const float* __restrict__ out_b,
                              const float* __restrict__ conv1_b, float* __restrict__ bc)
{
    int w = threadIdx.x >> 5, lane = threadIdx.x & 31;
    int o = blockIdx.x * 8 + w;
    const float* cw = conv1_w + (size_t)o*DD;
    float s = 0.f;
    #pragma unroll
    for (int j = 0; j < 8; ++j) {
        int m = j*32 + lane;
        s += cw[m] * out_b[m];
    }
    #pragma unroll
    for (int off = 16; off; off >>= 1) s += __shfl_xor_sync(0xffffffffu, s, off);
    if (lane == 0) bc[o] = s + conv1_b[o];
}

// ---------------- tf32 WMMA GEMM: 64x64 tile, 4 warps (round-9 version) ----
#define GBM 64
#define GBN 64
#define GBK 16
#define ALD 20
#define BLD 20
#define SLD 36

__global__ __launch_bounds__(128)
void sgemm_tc_kernel(const float* __restrict__ A, const float* __restrict__ B,
                     const float* __restrict__ bias, float* __restrict__ C,
                     int M, int N, int K, int relu,
                     const float* __restrict__ pos, const float* __restrict__ cam,
                     float* __restrict__ out2,
                     __half* __restrict__ outh)
{
    __shared__ float smem[4608];             // 18 KB
    float* As = smem;                        // [64][20]
    float* Bs = smem + 1280;                 // [64][20]

    int tid  = threadIdx.x;
    int w    = tid >> 5;
    int lane = tid & 31;
    int wm   = w >> 1;
    int wn   = w & 1;
    int bm = blockIdx.y * GBM, bn = blockIdx.x * GBN;

    int lrow = tid >> 2;            // 0..31
    int lcol = (tid & 3) << 2;      // 0,4,8,12

    wmma::fragment<wmma::accumulator, 16, 16, 8, float> c[2][2];
    #pragma unroll
    for (int i = 0; i < 2; ++i)
        #pragma unroll
        for (int j = 0; j < 2; ++j) wmma::fill_fragment(c[i][j], 0.f);

    for (int k0 = 0; k0 < K; k0 += GBK) {
        {
            float4 a = *(const float4*)(A + (size_t)(bm + lrow)*K + k0 + lcol);
            As[lrow*ALD + lcol+0] = wmma::__float_to_tf32(a.x);
            As[lrow*ALD + lcol+1] = wmma::__float_to_tf32(a.y);
            As[lrow*ALD + lcol+2] = wmma::__float_to_tf32(a.z);
            As[lrow*ALD + lcol+3] = wmma::__float_to_tf32(a.w);
            a = *(const float4*)(A + (size_t)(bm + lrow + 32)*K + k0 + lcol);
            As[(lrow+32)*ALD + lcol+0] = wmma::__float_to_tf32(a.x);
            As[(lrow+32)*ALD + lcol+1] = wmma::__float_to_tf32(a.y);
            As[(lrow+32)*ALD + lcol+2] = wmma::__float_to_tf32(a.z);
            As[(lrow+32)*ALD + lcol+3] = wmma::__float_to_tf32(a.w);
        }
        {
            float4 b = *(const float4*)(B + (size_t)(bn + lrow)*K + k0 + lcol);
            Bs[lrow*BLD + lcol+0] = wmma::__float_to_tf32(b.x);
            Bs[lrow*BLD + lcol+1] = wmma::__float_to_tf32(b.y);
            Bs[lrow*BLD + lcol+2] = wmma::__float_to_tf32(b.z);
            Bs[lrow*BLD + lcol+3] = wmma::__float_to_tf32(b.w);
            b = *(const float4*)(B + (size_t)(bn + lrow + 32)*K + k0 + lcol);
            Bs[(lrow+32)*BLD + lcol+0] = wmma::__float_to_tf32(b.x);
            Bs[(lrow+32)*BLD + lcol+1] = wmma::__float_to_tf32(b.y);
            Bs[(lrow+32)*BLD + lcol+2] = wmma::__float_to_tf32(b.z);
            Bs[(lrow+32)*BLD + lcol+3] = wmma::__float_to_tf32(b.w);
        }
        __syncthreads();

        #pragma unroll
        for (int kk = 0; kk < GBK; kk += 8) {
            wmma::fragment<wmma::matrix_a, 16, 16, 8, wmma::precision::tf32, wmma::row_major> a[2];
            wmma::fragment<wmma::matrix_b, 16, 16, 8, wmma::precision::tf32, wmma::col_major> b[2];
            #pragma unroll
            for (int ii = 0; ii < 2; ++ii)
                wmma::load_matrix_sync(a[ii], &As[(wm*32 + ii*16)*ALD + kk], ALD);
            #pragma unroll
            for (int jj = 0; jj < 2; ++jj)
                wmma::load_matrix_sync(b[jj], &Bs[(wn*32 + jj*16)*BLD + kk], BLD);
            #pragma unroll
            for (int ii = 0; ii < 2; ++ii)
                #pragma unroll
                for (int jj = 0; jj < 2; ++jj)
                    wmma::mma_sync(c[ii][jj], a[ii], b[jj], c[ii][jj]);
        }
        __syncthreads();
    }

    // epilogue via smem stage (reuse smem)
    float* ws = smem + w * (32*SLD);
    #pragma unroll
    for (int i = 0; i < 2; ++i)
        #pragma unroll
        for (int j = 0; j < 2; ++j)
            wmma::store_matrix_sync(ws + (i*16)*SLD + j*16, c[i][j], SLD, wmma::mem_row_major);
    __syncwarp();

    int r0   = lane >> 3;          // 0..3
    int col4 = (lane & 7) << 2;    // 0..28
    int ncol = bn + wn*32 + col4;
    float4 bb = *(const float4*)(bias + ncol);
    #pragma unroll
    for (int it = 0; it < 8; ++it) {
        int row = r0 + it*4;
        int m = bm + wm*32 + row;
        float4 v = *(float4*)&ws[row*SLD + col4];
        v.x += bb.x; v.y += bb.y; v.z += bb.z; v.w += bb.w;
        if (relu) { v.x = fmaxf(v.x,0.f); v.y = fmaxf(v.y,0.f); v.z = fmaxf(v.z,0.f); v.w = fmaxf(v.w,0.f); }
        if (C)
            *(float4*)(C + (size_t)m*N + ncol) = v;
        if (outh) {
            __half2* dst = (__half2*)(outh + (size_t)m*N + ncol);
            dst[0] = __floats2half2_rn(v.x, v.y);
            dst[1] = __floats2half2_rn(v.z, v.w);
        }
        if (out2) {
            int pix = m % HWW, cm = m / HWW;
            float4 p = *(const float4*)(pos + (size_t)pix*DD + ncol);
            float4 e = *(const float4*)(cam + (size_t)cm*DD + ncol);
            float4 q;
            q.x = v.x + p.x + e.x; q.y = v.y + p.y + e.y;
            q.z = v.z + p.z + e.z; q.w = v.w + p.w + e.w;
            *(float4*)(out2 + (size_t)m*N + ncol) = q;
        }
    }
}

// mean over HW per camera: two-stage
__global__ void mean_part_kernel(const float* __restrict__ qry, float* __restrict__ part)
{
    int cm = blockIdx.x, blk = blockIdx.y, c = threadIdx.x;
    int p0 = blk * 50;
    float s = 0.f;
    #pragma unroll 5
    for (int p = 0; p < 50; ++p)
        s += qry[(size_t)(cm*HWW + p0 + p)*DD + c];
    part[(size_t)(cm*16 + blk)*DD + c] = s;
}

__global__ void mean_reduce_kernel(const float* __restrict__ part, float* __restrict__ meanb)
{
    int cm = blockIdx.x, c = threadIdx.x;
    float s = 0.f;
    #pragma unroll
    for (int i = 0; i < 16; ++i) s += part[(size_t)(cm*16 + i)*DD + c];
    meanb[cm*DD + c] = s * (1.0f/(float)HWW);
}

__global__ void gtok_kernel(const float* __restrict__ meanb, const float* __restrict__ w,
                            const float* __restrict__ b, float* __restrict__ gtok)
{
    int cm = blockIdx.x, o = threadIdx.x;
    float s = b[o];
    const float* mrow = meanb + cm*DD;
    const float* wrow = w + (size_t)o*DD;
    #pragma unroll 4
    for (int c = 0; c < DD; ++c) s += mrow[c] * wrow[c];
    gtok[cm*DD + o] = s;
}

// fused deformable gather + attention over interleaved fp16 KV.
// 1 warp per (q, head); lane = channel; one __half2 load per tap = (k, v).
__global__ __launch_bounds__(256)
void attn_kernel(const float* __restrict__ qry, const __half* __restrict__ kv,
                 const float* __restrict__ offs,
                 const float* __restrict__ gtok, float* __restrict__ attn_out)
{
    int q    = blockIdx.x;
    int h    = threadIdx.y;
    int lane = threadIdx.x;
    int pix = q % HWW;
    int row = pix / WW, col = pix % WW;
    float qd = qry[(size_t)q*DD + h*HDIM + lane] * 0.17677669529663687f;

    float logit[30], vv[30];
    const float* offq = offs + (size_t)q*NOFF + h*(NCAM*NP*2);

    #pragma unroll
    for (int l = 0; l < NCAM; ++l) {
        const __half* kvb = kv + (size_t)(l*HWW)*NKV + h*64 + 2*lane;
        float ks[NP], vs[NP];
        #pragma unroll
        for (int p = 0; p < NP; ++p) {
            float ox = offq[l*NP*2 + p*2 + 0];
            float oy = offq[l*NP*2 + p*2 + 1];
            float px = (float)col + ox;
            float py = (float)row + oy;
            float x0f = floorf(px), y0f = floorf(py);
            float fx = px - x0f, fy = py - y0f;
            int x0 = (int)x0f, y0 = (int)y0f;
            float ka = 0.f, va = 0.f;
            #pragma unroll
            for (int dy = 0; dy < 2; ++dy) {
                #pragma unroll
                for (int dx = 0; dx < 2; ++dx) {
                    int xi = x0 + dx, yi = y0 + dy;
                    if (xi >= 0 && xi < WW && yi >= 0 && yi < HH) {
                        float wgt = (dx ? fx : 1.f - fx) * (dy ? fy : 1.f - fy);
                        size_t idx = (size_t)(yi*WW + xi) * NKV;
                        __half2 p2 = __ldg((const __half2*)(kvb + idx));
                        float2 f2 = __half22float2(p2);
                        ka = fmaf(wgt, f2.x, ka);
                        va = fmaf(wgt, f2.y, va);
                    }
                }
            }
            ks[p] = ka; vs[p] = va;
        }
        #pragma unroll
        for (int p = 0; p < NP; ++p) {
            float d = qd * ks[p];
            #pragma unroll
            for (int o = 16; o; o >>= 1) d += __shfl_xor_sync(0xffffffffu, d, o);
            logit[l*5 + p] = d;
            vv[l*5 + p] = vs[p];
        }
        float kg = gtok[l*DD + h*HDIM + lane];
        float d = qd * kg;
        #pragma unroll
        for (int o = 16; o; o >>= 1) d += __shfl_xor_sync(0xffffffffu, d, o);
        logit[l*5 + 4] = d;
        vv[l*5 + 4] = kg;
    }
    float m = -1e30f;
    #pragma unroll
    for (int i = 0; i < 30; ++i) m = fmaxf(m, logit[i]);
    float s = 0.f, o = 0.f;
    #pragma unroll
    for (int i = 0; i < 30; ++i) { float e = __expf(logit[i] - m); s += e; o = fmaf(e, vv[i], o); }
    attn_out[(size_t)q*DD + h*HDIM + lane] = o / s;
}

// block-wide sum over 256 threads
__device__ __forceinline__ float block_sum_256(float v, float* sh)
{
    int lane = threadIdx.x & 31, wid = threadIdx.x >> 5;
    #pragma unroll
    for (int o = 16; o; o >>= 1) v += __shfl_xor_sync(0xffffffffu, v, o);
    if (lane == 0) sh[wid] = v;
    __syncthreads();
    float t = 0.f;
    #pragma unroll
    for (int i = 0; i < 8; ++i) t += sh[i];
    __syncthreads();
    return t;
}

__global__ __launch_bounds__(256)
void ln_kernel(const float* __restrict__ A, const float* __restrict__ Bd,
               const float* __restrict__ gam, const float* __restrict__ bet,
               float* __restrict__ out)
{
    __shared__ float sh[8];
    int q = blockIdx.x, c = threadIdx.x;
    float v = A[(size_t)q*DD + c] + Bd[(size_t)q*DD + c];
    float mu = block_sum_256(v, sh) * (1.f/(float)DD);
    float d = v - mu;
    float var = block_sum_256(d*d, sh) * (1.f/(float)DD);
    out[(size_t)q*DD + c] = d * rsqrtf(var + 1e-5f) * gam[c] + bet[c];
}

__global__ __launch_bounds__(256)
void ln_out_kernel(const float* __restrict__ A, const float* __restrict__ Bd,
                   const float* __restrict__ gam, const float* __restrict__ bet,
                   float* __restrict__ out)
{
    __shared__ float sh[8];
    int q = blockIdx.x, c = threadIdx.x;
    float v = A[(size_t)q*DD + c] + Bd[(size_t)q*DD + c];
    float mu = block_sum_256(v, sh) * (1.f/(float)DD);
    float d = v - mu;
    float var = block_sum_256(d*d, sh) * (1.f/(float)DD);
    float r = d * rsqrtf(var + 1e-5f) * gam[c] + bet[c];
    int cm = q / HWW, pix = q % HWW;
    out[(size_t)(cm*DD + c)*HWW + pix] = r;
}

// ------------------------- launch ------------------------------------------
extern "C" void kernel_launch(void* const* d_in, const int* in_sizes, int n_in,
                              void* d_out, int out_size)
{
    const float* x       = (const float*)d_in[0];
    const float* conv0_w = (const float*)d_in[1];
    const float* conv0_b = (const float*)d_in[2];
    const float* conv2_w = (const float*)d_in[3];
    const float* conv2_b = (const float*)d_in[4];
    const float* cam_emb = (const float*)d_in[5];
    const float* off_w   = (const float*)d_in[6];
    const float* off_b   = (const float*)d_in[7];
    const float* val_w   = (const float*)d_in[8];
    const float* val_b   = (const float*)d_in[9];
    const float* key_w   = (const float*)d_in[10];
    const float* key_b   = (const float*)d_in[11];
    const float* out_w   = (const float*)d_in[12];
    const float* out_b   = (const float*)d_in[13];
    const float* conv1_w = (const float*)d_in[14];
    const float* conv1_b = (const float*)d_in[15];
    const float* norm0_g = (const float*)d_in[16];
    const float* norm0_b = (const float*)d_in[17];
    const float* lin1_w  = (const float*)d_in[18];
    const float* lin1_b  = (const float*)d_in[19];
    const float* lin2_w  = (const float*)d_in[20];
    const float* lin2_b  = (const float*)d_in[21];
    const float* norm2_g = (const float*)d_in[22];
    const float* norm2_b = (const float*)d_in[23];

    float *res, *srcb, *qry, *offb, *posb, *part, *meanb, *gtokb,
          *attb, *t1, *t2, *lnb, *wc, *bc, *wkv, *bkv;
    __half *kvh;
    cudaGetSymbolAddress((void**)&res,   g_res);
    cudaGetSymbolAddress((void**)&srcb,  g_srcb);
    cudaGetSymbolAddress((void**)&qry,   g_qry);
    cudaGetSymbolAddress((void**)&kvh,   g_kvh);
    cudaGetSymbolAddress((void**)&offb,  g_offb);
    cudaGetSymbolAddress((void**)&posb,  g_posb);
    cudaGetSymbolAddress((void**)&part,  g_part);
    cudaGetSymbolAddress((void**)&meanb, g_meanb);
    cudaGetSymbolAddress((void**)&gtokb, g_gtokb);
    cudaGetSymbolAddress((void**)&attb,  g_attb);
    cudaGetSymbolAddress((void**)&t1,    g_t1b);
    cudaGetSymbolAddress((void**)&t2,    g_t2b);
    cudaGetSymbolAddress((void**)&lnb,   g_lnb);
    cudaGetSymbolAddress((void**)&wc,    g_wc);
    cudaGetSymbolAddress((void**)&bc,    g_bc);
    cudaGetSymbolAddress((void**)&wkv,   g_wkv);
    cudaGetSymbolAddress((void**)&bkv,   g_bkv);

    dim3 tb(32, 8);
    const int MB = LQ / GBM;   // 75

    // launches 0-2: prep (so launch index 3 = conv0 GEMM stays in profiled slot)
    pack_kvw_kernel<<<NKV, DD>>>(key_w, val_w, key_b, val_b, wkv, bkv);
    pos_kernel<<<HWW, DD>>>(posb);
    transpose_in_kernel<<<dim3(25, 8, NCAM), tb>>>(x, res);

    // launch 3: conv0 + fused (pos + cam_emb) second output  << profiled slot
    sgemm_tc_kernel<<<dim3(DD/GBN, MB), 128>>>(res, conv0_w, conv0_b, srcb, LQ, DD, DD, 0,
                                               posb, cam_emb, qry, 0);

    // combined key|val GEMM (N=512) -> interleaved fp16 KV directly
    sgemm_tc_kernel<<<dim3(NKV/GBN, MB), 128>>>(srcb, wkv, bkv, (float*)0, LQ, NKV, DD, 0,
                                                0, 0, 0, kvh);
    // offsets
    sgemm_tc_kernel<<<dim3(NOFF/GBN, MB), 128>>>(qry, off_w, off_b, offb, LQ, NOFF, DD, 0,
                                                 0, 0, 0, 0);

    // g-token path
    mean_part_kernel<<<dim3(NCAM,16), DD>>>(qry, part);
    mean_reduce_kernel<<<NCAM, DD>>>(part, meanb);
    gtok_kernel<<<NCAM, DD>>>(meanb, conv2_w, conv2_b, gtokb);

    // fused gather + attention
    attn_kernel<<<LQ, tb>>>(qry, kvh, offb, gtokb, attb);

    // weight folding
    fold_w_kernel<<<dim3(4,4), 256>>>(conv1_w, out_w, wc);
    fold_b_kernel<<<32, 256>>>(conv1_w, out_b, conv1_b, bc);

    // combined out_w+conv1 projection
    sgemm_tc_kernel<<<dim3(DD/GBN, MB), 128>>>(attb, wc, bc, t2, LQ, DD, DD, 0, 0, 0, 0, 0);

    ln_kernel<<<LQ, DD>>>(res, t2, norm0_g, norm0_b, lnb);

    sgemm_tc_kernel<<<dim3(DD/GBN, MB), 128>>>(lnb, lin1_w, lin1_b, t1, LQ, DD, DD, 1, 0, 0, 0, 0);
    sgemm_tc_kernel<<<dim3(DD/GBN, MB), 128>>>(t1, lin2_w, lin2_b, t2, LQ, DD, DD, 0, 0, 0, 0, 0);

    ln_out_kernel<<<LQ, DD>>>(lnb, t2, norm2_g, norm2_b, (float*)d_out);
}